// round 14
// baseline (speedup 1.0000x reference)
#include <cuda_runtime.h>
#include <cstdint>

// Fixed shapes per reference: B=4096, IN=HID=8192, fp32
#define IN_DIM   8192
#define HID_DIM  8192
#define COL4     (IN_DIM / 4)                    // 2048 float4 per row
#define ROW_GRPS 128
#define ROWS_PER_GRP (HID_DIM / ROW_GRPS)        // 64

#define RD_ROWS   8                              // rows per rowdot CTA
#define STAGE_F   1024                           // floats per row per stage
#define STAGE_B   (STAGE_F * 4)                  // 4 KB per row-segment
#define NSTAGE    (IN_DIM / STAGE_F)             // 8
#define TILE_B    (RD_ROWS * STAGE_B)            // 32 KB per stage tile

// Device-global scratch (allocation-free rule: device globals allowed)
__device__ float g_partial[ROW_GRPS * IN_DIM];   // 4 MB
__device__ float g_wsum[IN_DIM];                 // 32 KB

// ---------------- Kernel 1: partial column sums of W (frozen, 81.6%) --------
__global__ __launch_bounds__(256) void colsum_partial(const float* __restrict__ w) {
    const int col4 = blockIdx.x * 256 + threadIdx.x;
    const int r0   = blockIdx.y * ROWS_PER_GRP;
    const float4* __restrict__ w4 = reinterpret_cast<const float4*>(w);

    float4 acc = make_float4(0.f, 0.f, 0.f, 0.f);
    #pragma unroll 8
    for (int r = 0; r < ROWS_PER_GRP; ++r) {
        float4 v = __ldg(&w4[(size_t)(r0 + r) * COL4 + col4]);
        acc.x += v.x; acc.y += v.y; acc.z += v.z; acc.w += v.w;
    }
    reinterpret_cast<float4*>(g_partial)[(size_t)blockIdx.y * COL4 + col4] = acc;
}

// ---------------- Kernel 2: wide reduce (frozen, ~1 us) ----------------
__global__ __launch_bounds__(256) void reduce_partial() {
    const int t    = threadIdx.x;
    const int cl   = t & 63;
    const int gq   = t >> 6;
    const int col4 = blockIdx.x * 64 + cl;
    const float4* __restrict__ p4 = reinterpret_cast<const float4*>(g_partial);

    float4 acc = make_float4(0.f, 0.f, 0.f, 0.f);
    #pragma unroll 8
    for (int i = 0; i < 32; ++i) {
        float4 v = p4[(size_t)(gq * 32 + i) * COL4 + col4];
        acc.x += v.x; acc.y += v.y; acc.z += v.z; acc.w += v.w;
    }

    __shared__ float4 s[4][64];
    s[gq][cl] = acc;
    __syncthreads();

    if (t < 64) {
        float4 a = s[0][t], b = s[1][t], c = s[2][t], d = s[3][t];
        float4 r;
        r.x = (a.x + b.x) + (c.x + d.x);
        r.y = (a.y + b.y) + (c.y + d.y);
        r.z = (a.z + b.z) + (c.z + d.z);
        r.w = (a.w + b.w) + (c.w + d.w);
        reinterpret_cast<float4*>(g_wsum)[blockIdx.x * 64 + t] = r;
    }
}

// ---------------- Kernel 3: pipelined long-lived rowdot ----------------
// 512 CTAs x 8 rows. Double-buffered cp.async.bulk stages (32 KB each);
// warp w owns row w; per-CTA DRAM stream stays live across 8 stages.
__device__ __forceinline__ void rd_issue(const float* __restrict__ x,
                                         uint32_t sdst, uint32_t smbar,
                                         int rbase, int stage) {
    asm volatile("mbarrier.arrive.expect_tx.shared.b64 _, [%0], %1;"
                 :: "r"(smbar), "r"(TILE_B) : "memory");
    #pragma unroll
    for (int r = 0; r < RD_ROWS; ++r) {
        const float* src = x + (size_t)(rbase + r) * IN_DIM + stage * STAGE_F;
        asm volatile("cp.async.bulk.shared::cta.global.mbarrier::complete_tx::bytes "
                     "[%0], [%1], %2, [%3];"
                     :: "r"(sdst + r * STAGE_B), "l"(src),
                        "r"(STAGE_B), "r"(smbar) : "memory");
    }
}

__global__ __launch_bounds__(256) void rowdot_pipe(const float* __restrict__ x,
                                                   float* __restrict__ out) {
    __shared__ alignas(128) float sx[2][RD_ROWS][STAGE_F];   // 64 KB
    __shared__ alignas(8)  unsigned long long mbar[2];

    const int t     = threadIdx.x;
    const int lane  = t & 31;
    const int wid   = t >> 5;                    // warp w -> row w
    const int rbase = blockIdx.x * RD_ROWS;

    uint32_t smb[2];
    smb[0] = (uint32_t)__cvta_generic_to_shared(&mbar[0]);
    smb[1] = (uint32_t)__cvta_generic_to_shared(&mbar[1]);
    uint32_t sbuf[2];
    sbuf[0] = (uint32_t)__cvta_generic_to_shared(&sx[0][0][0]);
    sbuf[1] = (uint32_t)__cvta_generic_to_shared(&sx[1][0][0]);

    if (t == 0) {
        asm volatile("mbarrier.init.shared.b64 [%0], 1;" :: "r"(smb[0]) : "memory");
        asm volatile("mbarrier.init.shared.b64 [%0], 1;" :: "r"(smb[1]) : "memory");
        asm volatile("fence.proxy.async.shared::cta;" ::: "memory");
    }
    __syncthreads();

    if (t == 0) {
        rd_issue(x, sbuf[0], smb[0], rbase, 0);
        rd_issue(x, sbuf[1], smb[1], rbase, 1);
    }

    const float4* __restrict__ w4 = reinterpret_cast<const float4*>(g_wsum);
    float acc = 0.f;

    for (int s = 0; s < NSTAGE; ++s) {
        const int buf = s & 1;
        const uint32_t ph = (uint32_t)((s >> 1) & 1);

        // wait stage tile
        asm volatile(
            "{\n\t.reg .pred p;\n\t"
            "WAIT_%=:\n\t"
            "mbarrier.try_wait.parity.shared.b64 p, [%0], %1, 0x989680;\n\t"
            "@!p bra WAIT_%=;\n\t}"
            :: "r"(smb[buf]), "r"(ph) : "memory");

        const float4* __restrict__ xs =
            reinterpret_cast<const float4*>(sx[buf][wid]);
        const float4* __restrict__ ws = w4 + s * (STAGE_F / 4);

        #pragma unroll
        for (int i = 0; i < STAGE_F / 4 / 32; ++i) {     // 8 f4 per lane
            const int j = lane + 32 * i;
            float4 xv = xs[j];
            float4 wv = __ldg(&ws[j]);                   // L1-resident
            acc = fmaf(xv.x, wv.x, acc);
            acc = fmaf(xv.y, wv.y, acc);
            acc = fmaf(xv.z, wv.z, acc);
            acc = fmaf(xv.w, wv.w, acc);
        }

        __syncthreads();                                 // tile consumed
        if (t == 0 && s + 2 < NSTAGE)
            rd_issue(x, sbuf[buf], smb[buf], rbase, s + 2);
    }

    // warp w reduces row w and writes its output
    #pragma unroll
    for (int off = 16; off > 0; off >>= 1)
        acc += __shfl_xor_sync(0xFFFFFFFFu, acc, off);
    if (lane == 0)
        out[rbase + wid] = acc * 0.75f;                  // (/2) * 1.5
}

extern "C" void kernel_launch(void* const* d_in, const int* in_sizes, int n_in,
                              void* d_out, int out_size) {
    const float* x = (const float*)d_in[0];   // [B, IN]
    const float* w = (const float*)d_in[1];   // [HID, IN]
    float* out = (float*)d_out;               // [B, 1]
    const int B = in_sizes[0] / IN_DIM;

    dim3 g1(COL4 / 256, ROW_GRPS);            // (8, 128)
    colsum_partial<<<g1, 256>>>(w);
    reduce_partial<<<32, 256>>>();
    rowdot_pipe<<<B / RD_ROWS, 256>>>(x, out);
}